// round 9
// baseline (speedup 1.0000x reference)
#include <cuda_runtime.h>
#include <cuda_bf16.h>
#include <math.h>

// ---------------------------------------------------------------------------
// GraphGPS regressor forward, fp32 v8: f32x2 math, chip-filling GEMM tiles
// (vectorized smem fragment loads), double-buffered attention KV pipeline,
// wave-balanced split-KV (8 splits), vectorized v4.f32 scatter reductions.
// N=4096 nodes, E=131072 edges, D=256, H=8 heads (HD=32), L=2 layers.
// ---------------------------------------------------------------------------

#define NN   4096
#define DD   256
#define HH   8
#define HDIM 32
#define LL   2
#define FFH  512
#define QKVD 768
#define DEMB 128
#define TOUT 5
#define LN_EPS 1e-5f

// attention config: 2 queries per thread, 32-key double-buffered smem tiles
#define ATT_SPLITS 8
#define ATT_KV_PER_SPLIT (NN / ATT_SPLITS)   // 512
#define ATT_TILE 32                          // keys per smem tile
#define ATT_TPB 128                          // threads per block
#define ATT_QPB 256                          // queries per block (2/thread)

typedef unsigned long long ull;

// -------------------- packed f32x2 helpers ----------------------------------
__device__ __forceinline__ ull pack2(float lo, float hi) {
    ull r;
    asm("mov.b64 %0, {%1, %2};" : "=l"(r) : "f"(lo), "f"(hi));
    return r;
}
__device__ __forceinline__ void unpack2(ull v, float& lo, float& hi) {
    asm("mov.b64 {%0, %1}, %2;" : "=f"(lo), "=f"(hi) : "l"(v));
}
__device__ __forceinline__ ull ffma2(ull a, ull b, ull c) {
    ull d;
    asm("fma.rn.f32x2 %0, %1, %2, %3;" : "=l"(d) : "l"(a), "l"(b), "l"(c));
    return d;
}
__device__ __forceinline__ ull fmul2(ull a, ull b) {
    ull d;
    asm("mul.rn.f32x2 %0, %1, %2;" : "=l"(d) : "l"(a), "l"(b));
    return d;
}

// -------------------- scratch (static device globals) ----------------------
__device__ float g_x   [NN * DD];        // residual stream
__device__ float g_buf1[NN * QKVD];      // qkv / mlp hidden / ffn hidden
__device__ float g_buf2[NN * DD];        // misc
__device__ float g_agg [NN * DD];        // GIN aggregate / attn-out temp
__device__ float g_pacc[ATT_SPLITS * HH * NN * HDIM]; // attn partial acc
__device__ float g_pml [ATT_SPLITS * HH * NN * 2];    // attn partial (m, l)
__device__ int   g_idx64;                // 1 if edge_index is int64

// -------------------- activations ------------------------------------------
#define ACT_NONE 0
#define ACT_ELU  1
#define ACT_GELU 2

__device__ __forceinline__ float act_elu(float x) {
    return x > 0.0f ? x : expm1f(x);
}
__device__ __forceinline__ float act_gelu(float x) {
    // jax.nn.gelu approximate=True (tanh form)
    float x3 = x * x * x;
    return 0.5f * x * (1.0f + tanhf(0.7978845608028654f * (x + 0.044715f * x3)));
}

// -------------------- SGEMM: C[M,N] = act(A[M,K] @ W[N,K]^T + bias) --------
// BM=128, BN=64, BK=16, 256 threads, 8x4 per-thread microtile (2 f32x2 accs).
// Register-prefetch double buffering on the global->smem path; A fragment
// read as 2x LDS.128 (broadcast), B fragment as 2x LDS.64.
// Requires K % 8 == 0 and M % 128 == 0 (true for all call sites). N guarded;
// K tail beyond K (up to BK) is zero-padded (exact no-op in accumulation).
template <int ACT>
__global__ __launch_bounds__(256)
void sgemm_bias_act(const float* __restrict__ A, const float* __restrict__ W,
                    const float* __restrict__ bias, float* __restrict__ C,
                    int M, int N, int K)
{
    __shared__ __align__(16) float As[16][128];
    __shared__ __align__(16) float Ws[16][64];

    const int tid = threadIdx.x;
    const int bm = blockIdx.y * 128;
    const int bn = blockIdx.x * 64;
    const int tx = tid & 15;         // 0..15 -> n (4 cols each)
    const int ty = tid >> 4;         // 0..15 -> m (8 rows each)

    // A-tile mapping: 512 float4 (128 rows x 4), 2 per thread
    const int ar0 = tid >> 2;            // rows tid/4 and tid/4 + 64
    const int ac  = (tid & 3) * 4;       // col 0/4/8/12
    // W-tile mapping: 256 float4 (64 rows x 4), 1 per thread
    const int wr  = tid >> 2;            // 0..63
    const int wc  = (tid & 3) * 4;

    const int nk = (K + 15) / 16;

    float4 apf0, apf1, wpf;
    const float4 f4z = make_float4(0.f, 0.f, 0.f, 0.f);

    // prefetch tile 0
    {
        const int k0 = 0;
        apf0 = (k0 + ac < K) ? *(const float4*)(A + (size_t)(bm + ar0) * K + k0 + ac) : f4z;
        apf1 = (k0 + ac < K) ? *(const float4*)(A + (size_t)(bm + ar0 + 64) * K + k0 + ac) : f4z;
        wpf  = (bn + wr < N && k0 + wc < K)
                 ? *(const float4*)(W + (size_t)(bn + wr) * K + k0 + wc) : f4z;
    }

    ull acc2[8][2];
#pragma unroll
    for (int i = 0; i < 8; i++) { acc2[i][0] = 0ull; acc2[i][1] = 0ull; }

    for (int t = 0; t < nk; t++) {
        // commit prefetched tile to smem
        As[ac + 0][ar0] = apf0.x; As[ac + 1][ar0] = apf0.y;
        As[ac + 2][ar0] = apf0.z; As[ac + 3][ar0] = apf0.w;
        As[ac + 0][ar0 + 64] = apf1.x; As[ac + 1][ar0 + 64] = apf1.y;
        As[ac + 2][ar0 + 64] = apf1.z; As[ac + 3][ar0 + 64] = apf1.w;
        Ws[wc + 0][wr] = wpf.x; Ws[wc + 1][wr] = wpf.y;
        Ws[wc + 2][wr] = wpf.z; Ws[wc + 3][wr] = wpf.w;
        __syncthreads();

        // prefetch next tile (overlaps with compute below)
        if (t + 1 < nk) {
            const int k0 = (t + 1) * 16;
            apf0 = (k0 + ac < K) ? *(const float4*)(A + (size_t)(bm + ar0) * K + k0 + ac) : f4z;
            apf1 = (k0 + ac < K) ? *(const float4*)(A + (size_t)(bm + ar0 + 64) * K + k0 + ac) : f4z;
            wpf  = (bn + wr < N && k0 + wc < K)
                     ? *(const float4*)(W + (size_t)(bn + wr) * K + k0 + wc) : f4z;
        }

#pragma unroll
        for (int kk = 0; kk < 16; kk++) {
            const ull* bw = (const ull*)(&Ws[kk][tx * 4]);
            const ull b0 = bw[0];
            const ull b1 = bw[1];
            // A fragment: 8 contiguous floats, 2x LDS.128 (warp-broadcast)
            const float4* aw = (const float4*)(&As[kk][ty * 8]);
            const float4 a04 = aw[0];
            const float4 a14 = aw[1];
            const float af[8] = { a04.x, a04.y, a04.z, a04.w,
                                  a14.x, a14.y, a14.z, a14.w };
#pragma unroll
            for (int i = 0; i < 8; i++) {
                const ull a2 = pack2(af[i], af[i]);
                acc2[i][0] = ffma2(a2, b0, acc2[i][0]);
                acc2[i][1] = ffma2(a2, b1, acc2[i][1]);
            }
        }
        __syncthreads();
    }

#pragma unroll
    for (int i = 0; i < 8; i++) {
        const int row = bm + ty * 8 + i;
#pragma unroll
        for (int j = 0; j < 2; j++) {
            float v0, v1;
            unpack2(acc2[i][j], v0, v1);
            const int col = bn + tx * 4 + j * 2;
            if (col < N) {
                float v = v0 + bias[col];
                if (ACT == ACT_ELU)  v = act_elu(v);
                if (ACT == ACT_GELU) v = act_gelu(v);
                C[(size_t)row * N + col] = v;
            }
            if (col + 1 < N) {
                float v = v1 + bias[col + 1];
                if (ACT == ACT_ELU)  v = act_elu(v);
                if (ACT == ACT_GELU) v = act_gelu(v);
                C[(size_t)row * N + col + 1] = v;
            }
        }
    }
}

// -------------------- edge-index dtype detection ----------------------------
// int64 little-endian values in [0, 4096) have all-zero high words.
// Check 128 odd words; all zero => int64. (int32 random ids: P ~ 4096^-128.)
__global__ void detect_idx_kernel(const int* __restrict__ ei_words)
{
    int allzero = 1;
    for (int i = 1; i < 256; i += 2)
        if (ei_words[i] != 0) { allzero = 0; break; }
    g_idx64 = allzero;
}

// -------------------- elementwise / GIN kernels -----------------------------
// agg = (1 + eps[l]) * x   (pre-scatter init; scatter then accumulates)
__global__ void gin_init_kernel(const float* __restrict__ x,
                                const float* __restrict__ eps_arr, int l,
                                float* __restrict__ agg, int n4)
{
    int i = blockIdx.x * blockDim.x + threadIdx.x;
    if (i < n4) {
        const float eps = 1.0f + eps_arr[l];
        float4 v = ((const float4*)x)[i];
        v.x *= eps; v.y *= eps; v.z *= eps; v.w *= eps;
        ((float4*)agg)[i] = v;
    }
}

// GIN scatter: agg[dst] += x[src], one red.global.add.v4.f32 per 16B chunk
__global__ void scatter_add_kernel(const float* __restrict__ x,
                                   const int* __restrict__ ei,
                                   float* __restrict__ agg, int E)
{
    int idx = blockIdx.x * blockDim.x + threadIdx.x;
    if (idx >= E * (DD / 4)) return;
    int e = idx >> 6;        // DD/4 = 64 chunks
    int c = idx & 63;
    int src, dst;
    if (g_idx64) {
        const long long* e64 = (const long long*)ei;
        src = (int)e64[e];
        dst = (int)e64[E + e];
    } else {
        src = ei[e];
        dst = ei[E + e];
    }
    const float4 v = ((const float4*)x)[(size_t)src * (DD / 4) + c];
    float* a = agg + (size_t)dst * DD + c * 4;   // 16B-aligned
    asm volatile("red.global.add.v4.f32 [%0], {%1, %2, %3, %4};"
                 :: "l"(a), "f"(v.x), "f"(v.y), "f"(v.z), "f"(v.w)
                 : "memory");
}

// -------------------- layernorm (+opt ELU) + residual add ------------------
// x[row] += maybe_elu(LN(in[row]) * g + b).  One block per row, 256 threads.
__global__ __launch_bounds__(256)
void layernorm_res_kernel(const float* __restrict__ in,
                          const float* __restrict__ g,
                          const float* __restrict__ b,
                          float* __restrict__ x, int apply_elu)
{
    const int row = blockIdx.x;
    const int d = threadIdx.x;
    const float v = in[(size_t)row * DD + d];

    __shared__ float red[16];
    float s1 = v, s2 = v * v;
#pragma unroll
    for (int o = 16; o > 0; o >>= 1) {
        s1 += __shfl_xor_sync(0xFFFFFFFFu, s1, o);
        s2 += __shfl_xor_sync(0xFFFFFFFFu, s2, o);
    }
    const int wid = d >> 5;
    if ((d & 31) == 0) { red[wid] = s1; red[8 + wid] = s2; }
    __syncthreads();
    float t1 = 0.f, t2 = 0.f;
#pragma unroll
    for (int i = 0; i < 8; i++) { t1 += red[i]; t2 += red[8 + i]; }

    const float mu = t1 * (1.0f / DD);
    const float var = t2 * (1.0f / DD) - mu * mu;
    float y = (v - mu) * rsqrtf(var + LN_EPS) * g[d] + b[d];
    if (apply_elu) y = act_elu(y);
    x[(size_t)row * DD + d] += y;
}

// -------------------- flash attention (split-KV partials) ------------------
// 2 queries per thread (q and q+128), packed f32x2 math.
// 32-key smem tiles, double-buffered with register prefetch; softmax update
// runs in two 16-key sub-passes per tile (register-pressure bound).
// grid = (NN/ATT_QPB, HH, ATT_SPLITS), block = 128 threads.
__global__ __launch_bounds__(ATT_TPB)
void attn_partial_kernel(const float* __restrict__ qkv,
                         float* __restrict__ pacc, float* __restrict__ pml)
{
    __shared__ __align__(16) float4 Ks[2][ATT_TILE][HDIM / 4];
    __shared__ __align__(16) float4 Vs[2][ATT_TILE][HDIM / 4];

    const int t = threadIdx.x;
    const int q0 = blockIdx.x * ATT_QPB + t;
    const int q1 = q0 + ATT_TPB;
    const int h = blockIdx.y;
    const int s = blockIdx.z;
    const float scale = 0.17677669529663687f; // 1/sqrt(32)

    // packed query vectors: 16 f32x2 pairs each
    ull qa2[HDIM / 2], qb2[HDIM / 2];
    {
        const float4* pa = (const float4*)(qkv + (size_t)q0 * QKVD + h * HDIM);
        const float4* pb = (const float4*)(qkv + (size_t)q1 * QKVD + h * HDIM);
#pragma unroll
        for (int d4 = 0; d4 < HDIM / 4; d4++) {
            float4 va = pa[d4], vb = pb[d4];
            qa2[d4 * 2 + 0] = pack2(va.x * scale, va.y * scale);
            qa2[d4 * 2 + 1] = pack2(va.z * scale, va.w * scale);
            qb2[d4 * 2 + 0] = pack2(vb.x * scale, vb.y * scale);
            qb2[d4 * 2 + 1] = pack2(vb.z * scale, vb.w * scale);
        }
    }

    float ma = -1e30f, la = 0.0f, mb = -1e30f, lb = 0.0f;
    ull acca2[HDIM / 2], accb2[HDIM / 2];
#pragma unroll
    for (int d = 0; d < HDIM / 2; d++) { acca2[d] = 0ull; accb2[d] = 0ull; }

    const int key0 = s * ATT_KV_PER_SPLIT;
    const int jload = t >> 3;        // 0..15 (rows jload and jload+16)
    const int dload = t & 7;         // 0..7 (float4 index)

    // prefetch registers: 2 rows of K and V per thread
    float4 kpf[2], vpf[2];
    {
#pragma unroll
        for (int rep = 0; rep < 2; rep++) {
            const int row = rep * 16 + jload;
            const size_t base = (size_t)(key0 + row) * QKVD + h * HDIM + dload * 4;
            kpf[rep] = *(const float4*)(qkv + base + DD);
            vpf[rep] = *(const float4*)(qkv + base + 2 * DD);
        }
    }
    // commit tile 0 to buffer 0
#pragma unroll
    for (int rep = 0; rep < 2; rep++) {
        Ks[0][rep * 16 + jload][dload] = kpf[rep];
        Vs[0][rep * 16 + jload][dload] = vpf[rep];
    }
    __syncthreads();

    const int ntiles = ATT_KV_PER_SPLIT / ATT_TILE;
    for (int tt = 0; tt < ntiles; tt++) {
        const int buf = tt & 1;

        // prefetch next tile into registers (overlaps with compute below)
        if (tt + 1 < ntiles) {
            const int kt = (tt + 1) * ATT_TILE;
#pragma unroll
            for (int rep = 0; rep < 2; rep++) {
                const int row = rep * 16 + jload;
                const size_t base =
                    (size_t)(key0 + kt + row) * QKVD + h * HDIM + dload * 4;
                kpf[rep] = *(const float4*)(qkv + base + DD);
                vpf[rep] = *(const float4*)(qkv + base + 2 * DD);
            }
        }

        // two 16-key softmax sub-passes over the current buffer
#pragma unroll
        for (int half = 0; half < 2; half++) {
            const int jbase = half * 16;

            float sca[16], scb[16];
            float tma = -1e30f, tmb = -1e30f;
#pragma unroll
            for (int j = 0; j < 16; j++) {
                const ull* ks2 = (const ull*)(&Ks[buf][jbase + j][0]);
                ull sa0 = 0ull, sa1 = 0ull, sb0 = 0ull, sb1 = 0ull;
#pragma unroll
                for (int i = 0; i < HDIM / 2; i += 2) {
                    const ull k0 = ks2[i];
                    const ull k1 = ks2[i + 1];
                    sa0 = ffma2(qa2[i], k0, sa0);
                    sa1 = ffma2(qa2[i + 1], k1, sa1);
                    sb0 = ffma2(qb2[i], k0, sb0);
                    sb1 = ffma2(qb2[i + 1], k1, sb1);
                }
                float a0, a1, a2v, a3, b0, b1, b2v, b3;
                unpack2(sa0, a0, a1); unpack2(sa1, a2v, a3);
                unpack2(sb0, b0, b1); unpack2(sb1, b2v, b3);
                sca[j] = (a0 + a1) + (a2v + a3);
                scb[j] = (b0 + b1) + (b2v + b3);
                tma = fmaxf(tma, sca[j]);
                tmb = fmaxf(tmb, scb[j]);
            }

            const float man = fmaxf(ma, tma);
            const float mbn = fmaxf(mb, tmb);
            const float ca = __expf(ma - man);
            const float cb = __expf(mb - mbn);
            la *= ca; lb *= cb;
            {
                const ull ca2 = pack2(ca, ca);
                const ull cb2 = pack2(cb, cb);
#pragma unroll
                for (int d = 0; d < HDIM / 2; d++) {
                    acca2[d] = fmul2(acca2[d], ca2);
                    accb2[d] = fmul2(accb2[d], cb2);
                }
            }

#pragma unroll
            for (int j = 0; j < 16; j++) {
                const float pa = __expf(sca[j] - man);
                const float pb = __expf(scb[j] - mbn);
                la += pa; lb += pb;
                const ull pa2 = pack2(pa, pa);
                const ull pb2 = pack2(pb, pb);
                const ull* vs2 = (const ull*)(&Vs[buf][jbase + j][0]);
#pragma unroll
                for (int d = 0; d < HDIM / 2; d++) {
                    const ull v = vs2[d];
                    acca2[d] = ffma2(pa2, v, acca2[d]);
                    accb2[d] = ffma2(pb2, v, accb2[d]);
                }
            }
            ma = man; mb = mbn;
        }

        // commit prefetched tile to the other buffer, then one barrier
        if (tt + 1 < ntiles) {
            const int nbuf = buf ^ 1;
#pragma unroll
            for (int rep = 0; rep < 2; rep++) {
                Ks[nbuf][rep * 16 + jload][dload] = kpf[rep];
                Vs[nbuf][rep * 16 + jload][dload] = vpf[rep];
            }
            __syncthreads();
        }
    }

    const size_t pia = (((size_t)s * HH + h) * NN + q0);
    const size_t pib = (((size_t)s * HH + h) * NN + q1);
    pml[pia * 2 + 0] = ma; pml[pia * 2 + 1] = la;
    pml[pib * 2 + 0] = mb; pml[pib * 2 + 1] = lb;
#pragma unroll
    for (int d = 0; d < HDIM / 2; d++) {
        float x0, x1, y0, y1;
        unpack2(acca2[d], x0, x1);
        unpack2(accb2[d], y0, y1);
        pacc[pia * HDIM + d * 2 + 0] = x0;
        pacc[pia * HDIM + d * 2 + 1] = x1;
        pacc[pib * HDIM + d * 2 + 0] = y0;
        pacc[pib * HDIM + d * 2 + 1] = y1;
    }
}

// combine splits -> o[N, D] (layout [n, h*32+d])
// block = 256 threads = 8 (h,q) groups x 32 lanes; grid = HH*NN/8
__global__ __launch_bounds__(256)
void attn_combine_kernel(const float* __restrict__ pacc,
                         const float* __restrict__ pml,
                         float* __restrict__ o)
{
    const int grp = blockIdx.x * 8 + (threadIdx.x >> 5);
    const int lane = threadIdx.x & 31;
    const int h = grp >> 12;     // grp / NN
    const int q = grp & (NN - 1);

    float M = -1e30f;
#pragma unroll
    for (int s = 0; s < ATT_SPLITS; s++) {
        const size_t pi = (((size_t)s * HH + h) * NN + q);
        M = fmaxf(M, pml[pi * 2 + 0]);
    }
    float L = 0.0f, num = 0.0f;
#pragma unroll
    for (int s = 0; s < ATT_SPLITS; s++) {
        const size_t pi = (((size_t)s * HH + h) * NN + q);
        const float w = __expf(pml[pi * 2 + 0] - M);
        L += pml[pi * 2 + 1] * w;
        num = fmaf(w, pacc[pi * HDIM + lane], num);
    }
    o[(size_t)q * DD + h * HDIM + lane] = num / L;
}

// -------------------- launch ------------------------------------------------
extern "C" void kernel_launch(void* const* d_in, const int* in_sizes, int n_in,
                              void* d_out, int out_size)
{
    const float* x_in       = (const float*)d_in[0];
    const int*   edge_index = (const int*)d_in[1];   // int32 or int64 (detected)
    const float* in_w       = (const float*)d_in[2];
    const float* in_b       = (const float*)d_in[3];
    const float* head_w1    = (const float*)d_in[4];
    const float* head_b1    = (const float*)d_in[5];
    const float* head_w2    = (const float*)d_in[6];
    const float* head_b2    = (const float*)d_in[7];
    const float* mlp_w1     = (const float*)d_in[8];
    const float* mlp_b1     = (const float*)d_in[9];
    const float* mlp_w2     = (const float*)d_in[10];
    const float* mlp_b2     = (const float*)d_in[11];
    const float* gin_eps    = (const float*)d_in[12];
    const float* ln1_g      = (const float*)d_in[13];
    const float* ln1_b      = (const float*)d_in[14];
    const float* attn_in_w  = (const float*)d_in[15];
    const float* attn_in_b  = (const float*)d_in[16];
    const float* attn_out_w = (const float*)d_in[17];
    const float* attn_out_b = (const float*)d_in[18];
    const float* ln2_g      = (const float*)d_in[19];
    const float* ln2_b      = (const float*)d_in[20];
    const float* ffn_w1     = (const float*)d_in[21];
    const float* ffn_b1     = (const float*)d_in[22];
    const float* ffn_w2     = (const float*)d_in[23];
    const float* ffn_b2     = (const float*)d_in[24];
    const float* ln3_g      = (const float*)d_in[25];
    const float* ln3_b      = (const float*)d_in[26];

    const int E = in_sizes[1] / 2;

    float *X, *B1, *B2, *AGG, *PACC, *PML;
    cudaGetSymbolAddress((void**)&X,    g_x);
    cudaGetSymbolAddress((void**)&B1,   g_buf1);
    cudaGetSymbolAddress((void**)&B2,   g_buf2);
    cudaGetSymbolAddress((void**)&AGG,  g_agg);
    cudaGetSymbolAddress((void**)&PACC, g_pacc);
    cudaGetSymbolAddress((void**)&PML,  g_pml);

    const int ND = NN * DD;

    // edge-index dtype detection (writes g_idx64, read by scatter)
    detect_idx_kernel<<<1, 1>>>(edge_index);

    // input projection + ELU  (K=72)
    sgemm_bias_act<ACT_ELU><<<dim3(4, 32), 256>>>(x_in, in_w, in_b, X,
                                                  NN, DD, 72);

    for (int l = 0; l < LL; l++) {
        // ---- GIN conv: agg = (1+eps)*x, then scatter-add neighbors ----
        gin_init_kernel<<<(ND / 4 + 255) / 256, 256>>>(X, gin_eps, l, AGG,
                                                       ND / 4);
        scatter_add_kernel<<<(E * (DD / 4) + 255) / 256, 256>>>(X, edge_index,
                                                                AGG, E);
        sgemm_bias_act<ACT_ELU><<<dim3(4, 32), 256>>>(
            AGG, mlp_w1 + (size_t)l * DD * DD, mlp_b1 + l * DD, B1, NN, DD,
            DD);
        sgemm_bias_act<ACT_NONE><<<dim3(4, 32), 256>>>(
            B1, mlp_w2 + (size_t)l * DD * DD, mlp_b2 + l * DD, B2, NN, DD, DD);
        layernorm_res_kernel<<<NN, DD>>>(B2, ln1_g + l * DD, ln1_b + l * DD, X,
                                         1);

        // ---- global self-attention ----
        sgemm_bias_act<ACT_NONE><<<dim3(12, 32), 256>>>(
            X, attn_in_w + (size_t)l * QKVD * DD, attn_in_b + l * QKVD, B1,
            NN, QKVD, DD);
        attn_partial_kernel<<<dim3(NN / ATT_QPB, HH, ATT_SPLITS), ATT_TPB>>>(
            B1, PACC, PML);
        attn_combine_kernel<<<(HH * NN) / 8, 256>>>(PACC, PML, B2);
        sgemm_bias_act<ACT_NONE><<<dim3(4, 32), 256>>>(
            B2, attn_out_w + (size_t)l * DD * DD, attn_out_b + l * DD, AGG,
            NN, DD, DD);
        layernorm_res_kernel<<<NN, DD>>>(AGG, ln2_g + l * DD, ln2_b + l * DD,
                                         X, 0);

        // ---- FFN ----
        sgemm_bias_act<ACT_GELU><<<dim3(8, 32), 256>>>(
            X, ffn_w1 + (size_t)l * FFH * DD, ffn_b1 + l * FFH, B1, NN, FFH,
            DD);
        sgemm_bias_act<ACT_NONE><<<dim3(4, 32), 256>>>(
            B1, ffn_w2 + (size_t)l * DD * FFH, ffn_b2 + l * DD, B2, NN, DD,
            FFH);
        layernorm_res_kernel<<<NN, DD>>>(B2, ln3_g + l * DD, ln3_b + l * DD, X,
                                         0);
    }

    // head: 256 -> 128 (ELU) -> 5
    sgemm_bias_act<ACT_ELU><<<dim3(2, 32), 256>>>(X, head_w1, head_b1, B2,
                                                  NN, DEMB, DD);
    sgemm_bias_act<ACT_NONE><<<dim3(1, 32), 256>>>(B2, head_w2, head_b2,
                                                   (float*)d_out, NN, TOUT,
                                                   DEMB);
}

// round 13
// speedup vs baseline: 1.2224x; 1.2224x over previous
#include <cuda_runtime.h>
#include <cuda_bf16.h>
#include <math.h>

// ---------------------------------------------------------------------------
// GraphGPS regressor forward, v9: tf32 mma.sync GEMMs (m16n8k8), f32x2
// attention with double-buffered KV pipeline, wave-balanced split-KV,
// vectorized v4.f32 scatter reductions.
// N=4096 nodes, E=131072 edges, D=256, H=8 heads (HD=32), L=2 layers.
// ---------------------------------------------------------------------------

#define NN   4096
#define DD   256
#define HH   8
#define HDIM 32
#define LL   2
#define FFH  512
#define QKVD 768
#define DEMB 128
#define TOUT 5
#define LN_EPS 1e-5f

// attention config: 2 queries per thread, 32-key double-buffered smem tiles
#define ATT_SPLITS 8
#define ATT_KV_PER_SPLIT (NN / ATT_SPLITS)   // 512
#define ATT_TILE 32                          // keys per smem tile
#define ATT_TPB 128                          // threads per block
#define ATT_QPB 256                          // queries per block (2/thread)

typedef unsigned long long ull;
typedef unsigned int uint32;

// -------------------- packed f32x2 helpers ----------------------------------
__device__ __forceinline__ ull pack2(float lo, float hi) {
    ull r;
    asm("mov.b64 %0, {%1, %2};" : "=l"(r) : "f"(lo), "f"(hi));
    return r;
}
__device__ __forceinline__ void unpack2(ull v, float& lo, float& hi) {
    asm("mov.b64 {%0, %1}, %2;" : "=f"(lo), "=f"(hi) : "l"(v));
}
__device__ __forceinline__ ull ffma2(ull a, ull b, ull c) {
    ull d;
    asm("fma.rn.f32x2 %0, %1, %2, %3;" : "=l"(d) : "l"(a), "l"(b), "l"(c));
    return d;
}
__device__ __forceinline__ ull fmul2(ull a, ull b) {
    ull d;
    asm("mul.rn.f32x2 %0, %1, %2;" : "=l"(d) : "l"(a), "l"(b));
    return d;
}

// tf32 conversion (round-to-nearest, keeps fp32 range)
__device__ __forceinline__ uint32 f2tf32(float v) {
    uint32 r;
    asm("cvt.rna.tf32.f32 %0, %1;" : "=r"(r) : "f"(v));
    return r;
}

// -------------------- scratch (static device globals) ----------------------
__device__ float g_x   [NN * DD];        // residual stream
__device__ float g_buf1[NN * QKVD];      // qkv / mlp hidden / ffn hidden
__device__ float g_buf2[NN * DD];        // misc
__device__ float g_agg [NN * DD];        // GIN aggregate / attn-out temp
__device__ float g_pacc[ATT_SPLITS * HH * NN * HDIM]; // attn partial acc
__device__ float g_pml [ATT_SPLITS * HH * NN * 2];    // attn partial (m, l)
__device__ int   g_idx64;                // 1 if edge_index is int64

// -------------------- activations ------------------------------------------
#define ACT_NONE 0
#define ACT_ELU  1
#define ACT_GELU 2

__device__ __forceinline__ float act_elu(float x) {
    return x > 0.0f ? x : expm1f(x);
}
__device__ __forceinline__ float act_gelu(float x) {
    // jax.nn.gelu approximate=True (tanh form)
    float x3 = x * x * x;
    return 0.5f * x * (1.0f + tanhf(0.7978845608028654f * (x + 0.044715f * x3)));
}

// -------------------- tf32 tensor-core GEMM ---------------------------------
// C[M,N] = act(A[M,K] @ W[N,K]^T + bias), via mma.sync.m16n8k8.tf32.
// BM=BN=64, BK=16, 256 threads = 8 warps in 2(m)x4(n); each warp computes a
// 32x16 tile as 2x2 m16n8k8 MMAs per 8-wide k-step. Smem padded [64][20] for
// conflict-free fragment loads. Register-prefetch double buffering.
// Requires M % 64 == 0 (true: M=4096). N, K guarded (zero-pad tail: exact).
template <int ACT>
__global__ __launch_bounds__(256)
void sgemm_bias_act(const float* __restrict__ A, const float* __restrict__ W,
                    const float* __restrict__ bias, float* __restrict__ C,
                    int M, int N, int K)
{
    __shared__ __align__(16) uint32 As[64][20];   // tf32 bits, 16 k + 4 pad
    __shared__ __align__(16) uint32 Ws[64][20];

    const int tid = threadIdx.x;
    const int bm = blockIdx.y * 64;
    const int bn = blockIdx.x * 64;

    const int warp = tid >> 5;
    const int lane = tid & 31;
    const int lr = lane >> 2;        // 0..7
    const int lc = lane & 3;         // 0..3
    const int wm = (warp & 1) * 32;  // warp m-offset
    const int wn = (warp >> 1) * 16; // warp n-offset

    // global->smem mapping: 1 float4 per thread per tile for A and W
    const int grow = tid >> 2;           // 0..63
    const int gc   = (tid & 3) * 4;      // 0,4,8,12

    const int nk = (K + 15) / 16;
    const float4 f4z = make_float4(0.f, 0.f, 0.f, 0.f);

    float4 apf, wpf;
    {
        apf = (gc < K) ? *(const float4*)(A + (size_t)(bm + grow) * K + gc) : f4z;
        wpf = (bn + grow < N && gc < K)
                ? *(const float4*)(W + (size_t)(bn + grow) * K + gc) : f4z;
    }

    float acc[2][2][4];
#pragma unroll
    for (int mt = 0; mt < 2; mt++)
#pragma unroll
        for (int nt = 0; nt < 2; nt++)
#pragma unroll
            for (int f = 0; f < 4; f++) acc[mt][nt][f] = 0.0f;

    for (int t = 0; t < nk; t++) {
        // commit prefetched tile (fp32 -> tf32)
        As[grow][gc + 0] = f2tf32(apf.x);
        As[grow][gc + 1] = f2tf32(apf.y);
        As[grow][gc + 2] = f2tf32(apf.z);
        As[grow][gc + 3] = f2tf32(apf.w);
        Ws[grow][gc + 0] = f2tf32(wpf.x);
        Ws[grow][gc + 1] = f2tf32(wpf.y);
        Ws[grow][gc + 2] = f2tf32(wpf.z);
        Ws[grow][gc + 3] = f2tf32(wpf.w);
        __syncthreads();

        // prefetch next tile (overlaps with MMA below)
        if (t + 1 < nk) {
            const int k0 = (t + 1) * 16;
            apf = (k0 + gc < K)
                    ? *(const float4*)(A + (size_t)(bm + grow) * K + k0 + gc) : f4z;
            wpf = (bn + grow < N && k0 + gc < K)
                    ? *(const float4*)(W + (size_t)(bn + grow) * K + k0 + gc) : f4z;
        }

#pragma unroll
        for (int ks = 0; ks < 2; ks++) {
            const int k0 = ks * 8;
            // A fragments for 2 m-tiles
            uint32 a[2][4];
#pragma unroll
            for (int mt = 0; mt < 2; mt++) {
                const int r0 = wm + mt * 16 + lr;
                a[mt][0] = As[r0][k0 + lc];
                a[mt][1] = As[r0 + 8][k0 + lc];
                a[mt][2] = As[r0][k0 + lc + 4];
                a[mt][3] = As[r0 + 8][k0 + lc + 4];
            }
            // B fragments for 2 n-tiles
            uint32 b[2][2];
#pragma unroll
            for (int nt = 0; nt < 2; nt++) {
                const int nr = wn + nt * 8 + lr;
                b[nt][0] = Ws[nr][k0 + lc];
                b[nt][1] = Ws[nr][k0 + lc + 4];
            }
#pragma unroll
            for (int mt = 0; mt < 2; mt++)
#pragma unroll
                for (int nt = 0; nt < 2; nt++) {
                    asm volatile(
                        "mma.sync.aligned.m16n8k8.row.col.f32.tf32.tf32.f32 "
                        "{%0,%1,%2,%3}, {%4,%5,%6,%7}, {%8,%9}, {%0,%1,%2,%3};"
                        : "+f"(acc[mt][nt][0]), "+f"(acc[mt][nt][1]),
                          "+f"(acc[mt][nt][2]), "+f"(acc[mt][nt][3])
                        : "r"(a[mt][0]), "r"(a[mt][1]),
                          "r"(a[mt][2]), "r"(a[mt][3]),
                          "r"(b[nt][0]), "r"(b[nt][1]));
                }
        }
        __syncthreads();
    }

    // epilogue: bias + activation + store
#pragma unroll
    for (int mt = 0; mt < 2; mt++) {
#pragma unroll
        for (int nt = 0; nt < 2; nt++) {
            const int col0 = bn + wn + nt * 8 + 2 * lc;
            const int row0 = bm + wm + mt * 16 + lr;
#pragma unroll
            for (int f = 0; f < 4; f++) {
                const int row = row0 + (f >> 1) * 8;
                const int col = col0 + (f & 1);
                if (col < N) {
                    float v = acc[mt][nt][f] + bias[col];
                    if (ACT == ACT_ELU)  v = act_elu(v);
                    if (ACT == ACT_GELU) v = act_gelu(v);
                    C[(size_t)row * N + col] = v;
                }
            }
        }
    }
}

// -------------------- edge-index dtype detection ----------------------------
// int64 little-endian values in [0, 4096) have all-zero high words.
// Check 128 odd words; all zero => int64. (int32 random ids: P ~ 4096^-128.)
__global__ void detect_idx_kernel(const int* __restrict__ ei_words)
{
    int allzero = 1;
    for (int i = 1; i < 256; i += 2)
        if (ei_words[i] != 0) { allzero = 0; break; }
    g_idx64 = allzero;
}

// -------------------- elementwise / GIN kernels -----------------------------
// agg = (1 + eps[l]) * x   (pre-scatter init; scatter then accumulates)
__global__ void gin_init_kernel(const float* __restrict__ x,
                                const float* __restrict__ eps_arr, int l,
                                float* __restrict__ agg, int n4)
{
    int i = blockIdx.x * blockDim.x + threadIdx.x;
    if (i < n4) {
        const float eps = 1.0f + eps_arr[l];
        float4 v = ((const float4*)x)[i];
        v.x *= eps; v.y *= eps; v.z *= eps; v.w *= eps;
        ((float4*)agg)[i] = v;
    }
}

// GIN scatter: agg[dst] += x[src], one red.global.add.v4.f32 per 16B chunk
__global__ void scatter_add_kernel(const float* __restrict__ x,
                                   const int* __restrict__ ei,
                                   float* __restrict__ agg, int E)
{
    int idx = blockIdx.x * blockDim.x + threadIdx.x;
    if (idx >= E * (DD / 4)) return;
    int e = idx >> 6;        // DD/4 = 64 chunks
    int c = idx & 63;
    int src, dst;
    if (g_idx64) {
        const long long* e64 = (const long long*)ei;
        src = (int)e64[e];
        dst = (int)e64[E + e];
    } else {
        src = ei[e];
        dst = ei[E + e];
    }
    const float4 v = ((const float4*)x)[(size_t)src * (DD / 4) + c];
    float* a = agg + (size_t)dst * DD + c * 4;   // 16B-aligned
    asm volatile("red.global.add.v4.f32 [%0], {%1, %2, %3, %4};"
                 :: "l"(a), "f"(v.x), "f"(v.y), "f"(v.z), "f"(v.w)
                 : "memory");
}

// -------------------- layernorm (+opt ELU) + residual add ------------------
// x[row] += maybe_elu(LN(in[row]) * g + b).  One block per row, 256 threads.
__global__ __launch_bounds__(256)
void layernorm_res_kernel(const float* __restrict__ in,
                          const float* __restrict__ g,
                          const float* __restrict__ b,
                          float* __restrict__ x, int apply_elu)
{
    const int row = blockIdx.x;
    const int d = threadIdx.x;
    const float v = in[(size_t)row * DD + d];

    __shared__ float red[16];
    float s1 = v, s2 = v * v;
#pragma unroll
    for (int o = 16; o > 0; o >>= 1) {
        s1 += __shfl_xor_sync(0xFFFFFFFFu, s1, o);
        s2 += __shfl_xor_sync(0xFFFFFFFFu, s2, o);
    }
    const int wid = d >> 5;
    if ((d & 31) == 0) { red[wid] = s1; red[8 + wid] = s2; }
    __syncthreads();
    float t1 = 0.f, t2 = 0.f;
#pragma unroll
    for (int i = 0; i < 8; i++) { t1 += red[i]; t2 += red[8 + i]; }

    const float mu = t1 * (1.0f / DD);
    const float var = t2 * (1.0f / DD) - mu * mu;
    float y = (v - mu) * rsqrtf(var + LN_EPS) * g[d] + b[d];
    if (apply_elu) y = act_elu(y);
    x[(size_t)row * DD + d] += y;
}

// -------------------- flash attention (split-KV partials) ------------------
// 2 queries per thread (q and q+128), packed f32x2 math.
// 32-key smem tiles, double-buffered with register prefetch; softmax update
// runs in two 16-key sub-passes per tile (register-pressure bound).
// grid = (NN/ATT_QPB, HH, ATT_SPLITS), block = 128 threads.
__global__ __launch_bounds__(ATT_TPB)
void attn_partial_kernel(const float* __restrict__ qkv,
                         float* __restrict__ pacc, float* __restrict__ pml)
{
    __shared__ __align__(16) float4 Ks[2][ATT_TILE][HDIM / 4];
    __shared__ __align__(16) float4 Vs[2][ATT_TILE][HDIM / 4];

    const int t = threadIdx.x;
    const int q0 = blockIdx.x * ATT_QPB + t;
    const int q1 = q0 + ATT_TPB;
    const int h = blockIdx.y;
    const int s = blockIdx.z;
    const float scale = 0.17677669529663687f; // 1/sqrt(32)

    // packed query vectors: 16 f32x2 pairs each
    ull qa2[HDIM / 2], qb2[HDIM / 2];
    {
        const float4* pa = (const float4*)(qkv + (size_t)q0 * QKVD + h * HDIM);
        const float4* pb = (const float4*)(qkv + (size_t)q1 * QKVD + h * HDIM);
#pragma unroll
        for (int d4 = 0; d4 < HDIM / 4; d4++) {
            float4 va = pa[d4], vb = pb[d4];
            qa2[d4 * 2 + 0] = pack2(va.x * scale, va.y * scale);
            qa2[d4 * 2 + 1] = pack2(va.z * scale, va.w * scale);
            qb2[d4 * 2 + 0] = pack2(vb.x * scale, vb.y * scale);
            qb2[d4 * 2 + 1] = pack2(vb.z * scale, vb.w * scale);
        }
    }

    float ma = -1e30f, la = 0.0f, mb = -1e30f, lb = 0.0f;
    ull acca2[HDIM / 2], accb2[HDIM / 2];
#pragma unroll
    for (int d = 0; d < HDIM / 2; d++) { acca2[d] = 0ull; accb2[d] = 0ull; }

    const int key0 = s * ATT_KV_PER_SPLIT;
    const int jload = t >> 3;        // 0..15 (rows jload and jload+16)
    const int dload = t & 7;         // 0..7 (float4 index)

    // prefetch registers: 2 rows of K and V per thread
    float4 kpf[2], vpf[2];
    {
#pragma unroll
        for (int rep = 0; rep < 2; rep++) {
            const int row = rep * 16 + jload;
            const size_t base = (size_t)(key0 + row) * QKVD + h * HDIM + dload * 4;
            kpf[rep] = *(const float4*)(qkv + base + DD);
            vpf[rep] = *(const float4*)(qkv + base + 2 * DD);
        }
    }
    // commit tile 0 to buffer 0
#pragma unroll
    for (int rep = 0; rep < 2; rep++) {
        Ks[0][rep * 16 + jload][dload] = kpf[rep];
        Vs[0][rep * 16 + jload][dload] = vpf[rep];
    }
    __syncthreads();

    const int ntiles = ATT_KV_PER_SPLIT / ATT_TILE;
    for (int tt = 0; tt < ntiles; tt++) {
        const int buf = tt & 1;

        // prefetch next tile into registers (overlaps with compute below)
        if (tt + 1 < ntiles) {
            const int kt = (tt + 1) * ATT_TILE;
#pragma unroll
            for (int rep = 0; rep < 2; rep++) {
                const int row = rep * 16 + jload;
                const size_t base =
                    (size_t)(key0 + kt + row) * QKVD + h * HDIM + dload * 4;
                kpf[rep] = *(const float4*)(qkv + base + DD);
                vpf[rep] = *(const float4*)(qkv + base + 2 * DD);
            }
        }

        // two 16-key softmax sub-passes over the current buffer
#pragma unroll
        for (int half = 0; half < 2; half++) {
            const int jbase = half * 16;

            float sca[16], scb[16];
            float tma = -1e30f, tmb = -1e30f;
#pragma unroll
            for (int j = 0; j < 16; j++) {
                const ull* ks2 = (const ull*)(&Ks[buf][jbase + j][0]);
                ull sa0 = 0ull, sa1 = 0ull, sb0 = 0ull, sb1 = 0ull;
#pragma unroll
                for (int i = 0; i < HDIM / 2; i += 2) {
                    const ull k0 = ks2[i];
                    const ull k1 = ks2[i + 1];
                    sa0 = ffma2(qa2[i], k0, sa0);
                    sa1 = ffma2(qa2[i + 1], k1, sa1);
                    sb0 = ffma2(qb2[i], k0, sb0);
                    sb1 = ffma2(qb2[i + 1], k1, sb1);
                }
                float a0, a1, a2v, a3, b0, b1, b2v, b3;
                unpack2(sa0, a0, a1); unpack2(sa1, a2v, a3);
                unpack2(sb0, b0, b1); unpack2(sb1, b2v, b3);
                sca[j] = (a0 + a1) + (a2v + a3);
                scb[j] = (b0 + b1) + (b2v + b3);
                tma = fmaxf(tma, sca[j]);
                tmb = fmaxf(tmb, scb[j]);
            }

            const float man = fmaxf(ma, tma);
            const float mbn = fmaxf(mb, tmb);
            const float ca = __expf(ma - man);
            const float cb = __expf(mb - mbn);
            la *= ca; lb *= cb;
            {
                const ull ca2 = pack2(ca, ca);
                const ull cb2 = pack2(cb, cb);
#pragma unroll
                for (int d = 0; d < HDIM / 2; d++) {
                    acca2[d] = fmul2(acca2[d], ca2);
                    accb2[d] = fmul2(accb2[d], cb2);
                }
            }

#pragma unroll
            for (int j = 0; j < 16; j++) {
                const float pa = __expf(sca[j] - man);
                const float pb = __expf(scb[j] - mbn);
                la += pa; lb += pb;
                const ull pa2 = pack2(pa, pa);
                const ull pb2 = pack2(pb, pb);
                const ull* vs2 = (const ull*)(&Vs[buf][jbase + j][0]);
#pragma unroll
                for (int d = 0; d < HDIM / 2; d++) {
                    const ull v = vs2[d];
                    acca2[d] = ffma2(pa2, v, acca2[d]);
                    accb2[d] = ffma2(pb2, v, accb2[d]);
                }
            }
            ma = man; mb = mbn;
        }

        // commit prefetched tile to the other buffer, then one barrier
        if (tt + 1 < ntiles) {
            const int nbuf = buf ^ 1;
#pragma unroll
            for (int rep = 0; rep < 2; rep++) {
                Ks[nbuf][rep * 16 + jload][dload] = kpf[rep];
                Vs[nbuf][rep * 16 + jload][dload] = vpf[rep];
            }
            __syncthreads();
        }
    }

    const size_t pia = (((size_t)s * HH + h) * NN + q0);
    const size_t pib = (((size_t)s * HH + h) * NN + q1);
    pml[pia * 2 + 0] = ma; pml[pia * 2 + 1] = la;
    pml[pib * 2 + 0] = mb; pml[pib * 2 + 1] = lb;
#pragma unroll
    for (int d = 0; d < HDIM / 2; d++) {
        float x0, x1, y0, y1;
        unpack2(acca2[d], x0, x1);
        unpack2(accb2[d], y0, y1);
        pacc[pia * HDIM + d * 2 + 0] = x0;
        pacc[pia * HDIM + d * 2 + 1] = x1;
        pacc[pib * HDIM + d * 2 + 0] = y0;
        pacc[pib * HDIM + d * 2 + 1] = y1;
    }
}

// combine splits -> o[N, D] (layout [n, h*32+d])
// block = 256 threads = 8 (h,q) groups x 32 lanes; grid = HH*NN/8
__global__ __launch_bounds__(256)
void attn_combine_kernel(const float* __restrict__ pacc,
                         const float* __restrict__ pml,
                         float* __restrict__ o)
{
    const int grp = blockIdx.x * 8 + (threadIdx.x >> 5);
    const int lane = threadIdx.x & 31;
    const int h = grp >> 12;     // grp / NN
    const int q = grp & (NN - 1);

    float M = -1e30f;
#pragma unroll
    for (int s = 0; s < ATT_SPLITS; s++) {
        const size_t pi = (((size_t)s * HH + h) * NN + q);
        M = fmaxf(M, pml[pi * 2 + 0]);
    }
    float L = 0.0f, num = 0.0f;
#pragma unroll
    for (int s = 0; s < ATT_SPLITS; s++) {
        const size_t pi = (((size_t)s * HH + h) * NN + q);
        const float w = __expf(pml[pi * 2 + 0] - M);
        L += pml[pi * 2 + 1] * w;
        num = fmaf(w, pacc[pi * HDIM + lane], num);
    }
    o[(size_t)q * DD + h * HDIM + lane] = num / L;
}

// -------------------- launch ------------------------------------------------
extern "C" void kernel_launch(void* const* d_in, const int* in_sizes, int n_in,
                              void* d_out, int out_size)
{
    const float* x_in       = (const float*)d_in[0];
    const int*   edge_index = (const int*)d_in[1];   // int32 or int64 (detected)
    const float* in_w       = (const float*)d_in[2];
    const float* in_b       = (const float*)d_in[3];
    const float* head_w1    = (const float*)d_in[4];
    const float* head_b1    = (const float*)d_in[5];
    const float* head_w2    = (const float*)d_in[6];
    const float* head_b2    = (const float*)d_in[7];
    const float* mlp_w1     = (const float*)d_in[8];
    const float* mlp_b1     = (const float*)d_in[9];
    const float* mlp_w2     = (const float*)d_in[10];
    const float* mlp_b2     = (const float*)d_in[11];
    const float* gin_eps    = (const float*)d_in[12];
    const float* ln1_g      = (const float*)d_in[13];
    const float* ln1_b      = (const float*)d_in[14];
    const float* attn_in_w  = (const float*)d_in[15];
    const float* attn_in_b  = (const float*)d_in[16];
    const float* attn_out_w = (const float*)d_in[17];
    const float* attn_out_b = (const float*)d_in[18];
    const float* ln2_g      = (const float*)d_in[19];
    const float* ln2_b      = (const float*)d_in[20];
    const float* ffn_w1     = (const float*)d_in[21];
    const float* ffn_b1     = (const float*)d_in[22];
    const float* ffn_w2     = (const float*)d_in[23];
    const float* ffn_b2     = (const float*)d_in[24];
    const float* ln3_g      = (const float*)d_in[25];
    const float* ln3_b      = (const float*)d_in[26];

    const int E = in_sizes[1] / 2;

    float *X, *B1, *B2, *AGG, *PACC, *PML;
    cudaGetSymbolAddress((void**)&X,    g_x);
    cudaGetSymbolAddress((void**)&B1,   g_buf1);
    cudaGetSymbolAddress((void**)&B2,   g_buf2);
    cudaGetSymbolAddress((void**)&AGG,  g_agg);
    cudaGetSymbolAddress((void**)&PACC, g_pacc);
    cudaGetSymbolAddress((void**)&PML,  g_pml);

    const int ND = NN * DD;
    const int GM = NN / 64;   // 64 m-blocks

    // edge-index dtype detection (writes g_idx64, read by scatter)
    detect_idx_kernel<<<1, 1>>>(edge_index);

    // input projection + ELU  (K=72)
    sgemm_bias_act<ACT_ELU><<<dim3(4, GM), 256>>>(x_in, in_w, in_b, X,
                                                  NN, DD, 72);

    for (int l = 0; l < LL; l++) {
        // ---- GIN conv: agg = (1+eps)*x, then scatter-add neighbors ----
        gin_init_kernel<<<(ND / 4 + 255) / 256, 256>>>(X, gin_eps, l, AGG,
                                                       ND / 4);
        scatter_add_kernel<<<(E * (DD / 4) + 255) / 256, 256>>>(X, edge_index,
                                                                AGG, E);
        sgemm_bias_act<ACT_ELU><<<dim3(4, GM), 256>>>(
            AGG, mlp_w1 + (size_t)l * DD * DD, mlp_b1 + l * DD, B1, NN, DD,
            DD);
        sgemm_bias_act<ACT_NONE><<<dim3(4, GM), 256>>>(
            B1, mlp_w2 + (size_t)l * DD * DD, mlp_b2 + l * DD, B2, NN, DD, DD);
        layernorm_res_kernel<<<NN, DD>>>(B2, ln1_g + l * DD, ln1_b + l * DD, X,
                                         1);

        // ---- global self-attention ----
        sgemm_bias_act<ACT_NONE><<<dim3(12, GM), 256>>>(
            X, attn_in_w + (size_t)l * QKVD * DD, attn_in_b + l * QKVD, B1,
            NN, QKVD, DD);
        attn_partial_kernel<<<dim3(NN / ATT_QPB, HH, ATT_SPLITS), ATT_TPB>>>(
            B1, PACC, PML);
        attn_combine_kernel<<<(HH * NN) / 8, 256>>>(PACC, PML, B2);
        sgemm_bias_act<ACT_NONE><<<dim3(4, GM), 256>>>(
            B2, attn_out_w + (size_t)l * DD * DD, attn_out_b + l * DD, AGG,
            NN, DD, DD);
        layernorm_res_kernel<<<NN, DD>>>(AGG, ln2_g + l * DD, ln2_b + l * DD,
                                         X, 0);

        // ---- FFN ----
        sgemm_bias_act<ACT_GELU><<<dim3(8, GM), 256>>>(
            X, ffn_w1 + (size_t)l * FFH * DD, ffn_b1 + l * FFH, B1, NN, FFH,
            DD);
        sgemm_bias_act<ACT_NONE><<<dim3(4, GM), 256>>>(
            B1, ffn_w2 + (size_t)l * DD * FFH, ffn_b2 + l * DD, B2, NN, DD,
            FFH);
        layernorm_res_kernel<<<NN, DD>>>(B2, ln3_g + l * DD, ln3_b + l * DD, X,
                                         0);
    }

    // head: 256 -> 128 (ELU) -> 5
    sgemm_bias_act<ACT_ELU><<<dim3(2, GM), 256>>>(X, head_w1, head_b1, B2,
                                                  NN, DEMB, DD);
    sgemm_bias_act<ACT_NONE><<<dim3(1, GM), 256>>>(B2, head_w2, head_b2,
                                                   (float*)d_out, NN, TOUT,
                                                   DEMB);
}